// round 8
// baseline (speedup 1.0000x reference)
#include <cuda_runtime.h>
#include <cuda_fp16.h>
#include <cstdint>

// Problem constants
#define N_FEAT  65536
#define N_PROTO 512
#define DIMK    256

#define BLK_M   256                 // feature rows per CTA
#define BLK_N   128                 // prototypes per chunk
#define N_CHUNKS (N_PROTO / BLK_N)  // 4

// SMEM layout (bytes)
#define SM_FSQ   0                          // 256 floats = 1024 B
#define SM_PSQ   1024                       // 512 floats = 2048 B
#define SM_A     4096                       // 16 mtiles * 16 ksteps * 512 B = 131072
#define SM_B     (SM_A + 131072)            // 16 ntiles * 16 ksteps * 256 B = 65536
#define SMEM_TOTAL (SM_B + 65536)           // 200704 B

// pack float2 -> fp16x2 (x -> low half)
__device__ __forceinline__ uint32_t pk(float2 f) {
    __half2 h = __floats2half2_rn(f.x, f.y);
    return *(uint32_t*)&h;
}

// m16n8k16 fp16 MMA, fp32 accumulate
__device__ __forceinline__ void mma_f16(float d[4], const uint32_t a[4], const uint32_t b[2]) {
    asm volatile(
        "mma.sync.aligned.m16n8k16.row.col.f32.f16.f16.f32 "
        "{%0,%1,%2,%3}, {%4,%5,%6,%7}, {%8,%9}, {%0,%1,%2,%3};"
        : "+f"(d[0]), "+f"(d[1]), "+f"(d[2]), "+f"(d[3])
        : "r"(a[0]), "r"(a[1]), "r"(a[2]), "r"(a[3]),
          "r"(b[0]), "r"(b[1]));
}

// ---------------------------------------------------------------------------
// Fragment SMEM layout (identity lane mapping, no swizzle, conflict-free):
//   A slab (mtile t, kstep s): 32 lanes x uint4 {a0,a1,a2,a3} = 512 B
//   B slab (ntile u, kstep s): 32 lanes x uint2 {b0,b1}       = 256 B
// Warp grid 4(M) x 4(N); per-warp register tile T=4 mtiles x U=4 ntiles
// -> 6 SMEM bytes per MMA (16/U + 8/T), 16 independent MMAs per k-step.
// ---------------------------------------------------------------------------
__global__ void __launch_bounds__(512, 1) proto_dist_kernel(
    const float* __restrict__ feat,
    const float* __restrict__ proto,
    float* __restrict__ out1,    // [N, P]
    float* __restrict__ out2)    // [P, N]
{
    extern __shared__ char smem[];
    float* s_fsq = (float*)(smem + SM_FSQ);
    float* s_psq = (float*)(smem + SM_PSQ);

    const int tid  = threadIdx.x;
    const int lane = tid & 31;
    const int wid  = tid >> 5;
    const int g    = lane >> 2;
    const int tig  = lane & 3;
    const int m0   = blockIdx.x * BLK_M;

    // ---- Stage A tile (256 x 256) as fp16 fragments + exact fp32 feat norms ----
    {
        const int t = wid;                       // warp w stages mtile w
        const float* rA = feat + (size_t)(m0 + t * 16 + g) * DIMK;
        const float* rB = rA + 8 * DIMK;
        float sqA = 0.f, sqB = 0.f;
#pragma unroll
        for (int s = 0; s < 16; s++) {
            const int kA = s * 16 + 2 * tig;
            float2 f0 = *(const float2*)(rA + kA);
            float2 f1 = *(const float2*)(rB + kA);
            float2 f2 = *(const float2*)(rA + kA + 8);
            float2 f3 = *(const float2*)(rB + kA + 8);
            sqA += f0.x * f0.x + f0.y * f0.y + f2.x * f2.x + f2.y * f2.y;
            sqB += f1.x * f1.x + f1.y * f1.y + f3.x * f3.x + f3.y * f3.y;
            uint4 w;
            w.x = pk(f0); w.y = pk(f1); w.z = pk(f2); w.w = pk(f3);
            *(uint4*)(smem + SM_A + (size_t)((t * 16 + s) * 32 + lane) * 16) = w;
        }
        sqA += __shfl_xor_sync(0xffffffffu, sqA, 1);
        sqA += __shfl_xor_sync(0xffffffffu, sqA, 2);
        sqB += __shfl_xor_sync(0xffffffffu, sqB, 1);
        sqB += __shfl_xor_sync(0xffffffffu, sqB, 2);
        if (tig == 0) {
            s_fsq[t * 16 + g]     = sqA;
            s_fsq[t * 16 + g + 8] = sqB;
        }
    }

    // ---- All 512 prototype norms, exact fp32 (proto is L2-hot: 512 KB) ----
    {
        const float4* r = (const float4*)(proto + (size_t)tid * DIMK);
        float s0 = 0.f, s1 = 0.f, s2 = 0.f, s3 = 0.f;
#pragma unroll
        for (int j = 0; j < 64; j += 4) {
            float4 v0 = r[j], v1 = r[j + 1], v2 = r[j + 2], v3 = r[j + 3];
            s0 += v0.x * v0.x + v0.y * v0.y + v0.z * v0.z + v0.w * v0.w;
            s1 += v1.x * v1.x + v1.y * v1.y + v1.z * v1.z + v1.w * v1.w;
            s2 += v2.x * v2.x + v2.y * v2.y + v2.z * v2.z + v2.w * v2.w;
            s3 += v3.x * v3.x + v3.y * v3.y + v3.z * v3.z + v3.w * v3.w;
        }
        s_psq[tid] = (s0 + s1) + (s2 + s3);
    }

    // ---- B staging: warp w stages ntile u=w of chunk c ----
    auto stage_B = [&](int c) {
        const float* r = proto + (size_t)(c * BLK_N + wid * 8 + g) * DIMK;
#pragma unroll
        for (int s = 0; s < 16; s++) {
            const int kA = s * 16 + 2 * tig;
            float2 f0 = *(const float2*)(r + kA);
            float2 f1 = *(const float2*)(r + kA + 8);
            uint2 w;
            w.x = pk(f0); w.y = pk(f1);
            *(uint2*)(smem + SM_B + (size_t)((wid * 16 + s) * 32 + lane) * 8) = w;
        }
    };

    stage_B(0);

    // Warp grid: 4 (M) x 4 (N); per warp T=4 mtiles, U=4 ntiles
    const int mi = wid >> 2;
    const int nj = wid & 3;

    __syncthreads();   // A frags + B(chunk 0) + norms visible

    for (int c = 0; c < N_CHUNKS; c++) {
        const int p0 = c * BLK_N;

        float acc[4][4][4];
#pragma unroll
        for (int tp = 0; tp < 4; tp++)
#pragma unroll
            for (int up = 0; up < 4; up++)
#pragma unroll
                for (int e = 0; e < 4; e++) acc[tp][up][e] = 0.f;

#pragma unroll
        for (int s = 0; s < 16; s++) {
            uint4 a[4];
#pragma unroll
            for (int tp = 0; tp < 4; tp++)
                a[tp] = *(const uint4*)(smem + SM_A +
                         (size_t)(((mi * 4 + tp) * 16 + s) * 32 + lane) * 16);
            uint2 b[4];
#pragma unroll
            for (int up = 0; up < 4; up++)
                b[up] = *(const uint2*)(smem + SM_B +
                         (size_t)(((nj * 4 + up) * 16 + s) * 32 + lane) * 8);
#pragma unroll
            for (int tp = 0; tp < 4; tp++)
#pragma unroll
                for (int up = 0; up < 4; up++)
                    mma_f16(acc[tp][up], (const uint32_t*)&a[tp], (const uint32_t*)&b[up]);
        }

        __syncthreads();   // B(chunk c) fully consumed; buffer free to rewrite

        // ---- Fused distance epilogue: direct stores for BOTH outputs ----
        // (reads only acc + norms; overlaps with other warps' stage_B below)
#pragma unroll
        for (int tp = 0; tp < 4; tp++) {
            const int ml0 = mi * 64 + tp * 16 + g;
            const int ml1 = ml0 + 8;
            const float fs0 = s_fsq[ml0];
            const float fs1 = s_fsq[ml1];
            float* o1a = out1 + (size_t)(m0 + ml0) * N_PROTO + p0;
            float* o1b = out1 + (size_t)(m0 + ml1) * N_PROTO + p0;
#pragma unroll
            for (int up = 0; up < 4; up++) {
                const int pl = nj * 32 + up * 8 + 2 * tig;
                const float2 ps = *(const float2*)(s_psq + p0 + pl);
                const float d0 = fs0 + ps.x - 2.0f * acc[tp][up][0];
                const float d1 = fs0 + ps.y - 2.0f * acc[tp][up][1];
                const float d2 = fs1 + ps.x - 2.0f * acc[tp][up][2];
                const float d3 = fs1 + ps.y - 2.0f * acc[tp][up][3];
                // out1 [N,P]: 4 tig-lanes x float2 = full 32B sector per row
                *(float2*)(o1a + pl) = make_float2(d0, d1);
                *(float2*)(o1b + pl) = make_float2(d2, d3);
                // out2 [P,N]: 8 g-lanes x 4B = full 32B sector per column
                float* o2 = out2 + (size_t)(p0 + pl) * N_FEAT + m0;
                o2[ml0]          = d0;
                o2[N_FEAT + ml0] = d1;
                o2[ml1]          = d2;
                o2[N_FEAT + ml1] = d3;
            }
        }

        if (c + 1 < N_CHUNKS) {
            stage_B(c + 1);     // overlaps epilogue stores of trailing warps
            __syncthreads();    // B(chunk c+1) visible
        }
    }
}

// ---------------------------------------------------------------------------
// Launch
// ---------------------------------------------------------------------------
extern "C" void kernel_launch(void* const* d_in, const int* in_sizes, int n_in,
                              void* d_out, int out_size)
{
    (void)in_sizes; (void)n_in; (void)out_size;
    const float* feat  = (const float*)d_in[0];
    const float* proto = (const float*)d_in[1];
    float* out1 = (float*)d_out;
    float* out2 = out1 + (size_t)N_FEAT * N_PROTO;

    cudaFuncSetAttribute(proto_dist_kernel,
                         cudaFuncAttributeMaxDynamicSharedMemorySize, SMEM_TOTAL);

    proto_dist_kernel<<<N_FEAT / BLK_M, 512, SMEM_TOTAL>>>(feat, proto, out1, out2);
}